// round 2
// baseline (speedup 1.0000x reference)
#include <cuda_runtime.h>
#include <cuda_bf16.h>
#include <stdint.h>

// Problem constants (shapes are fixed by the dataset)
#define FIN   256
#define FQK   256
#define NQK   (2 * FQK)          // 512
#define MAXN  20000
#define SCALING 0.0625f          // FQK^-0.5 = 1/16

// Scratch: qk projection [N, 512] and per-node exp-sums. __device__ globals
// (no allocation allowed in kernel_launch).
__device__ float g_qk[(size_t)MAXN * NQK];
__device__ float g_expsum[MAXN];

// ---------------------------------------------------------------------------
// Kernel 1: qk = x @ W^T   (x: [N,256] row-major, W: [512,256] row-major)
// C[i,j] = dot(x[i,:], W[j,:]); q half (j<256) scaled by 1/16.
// Tiled 64x64, BK=32, 256 threads, 4x4 per-thread microtile.
// ---------------------------------------------------------------------------
#define BM 64
#define BN 64
#define BK 32

__global__ __launch_bounds__(256)
void gemm_qk_kernel(const float* __restrict__ x,
                    const float* __restrict__ W,
                    float* __restrict__ qk,
                    int N)
{
    __shared__ float As[BK][BM];   // [k][m]
    __shared__ float Bs[BK][BN];   // [k][n]

    const int tid = threadIdx.x;
    const int bm  = blockIdx.y * BM;
    const int bn  = blockIdx.x * BN;

    const int lr = tid & 63;       // row within tile for loading
    const int lc = tid >> 6;       // 0..3 -> float4 column group

    const int tx = tid & 15;       // 16 cols of threads
    const int ty = tid >> 4;       // 16 rows of threads

    float acc[4][4];
#pragma unroll
    for (int i = 0; i < 4; i++)
#pragma unroll
        for (int j = 0; j < 4; j++) acc[i][j] = 0.0f;

    for (int kb = 0; kb < FIN; kb += BK) {
        // Load A (x) and B (W) tiles, transposed into [k][m] layout.
#pragma unroll
        for (int h = 0; h < 2; h++) {
            const int c4 = lc + h * 4;           // float4 index within BK
            const int gr = bm + lr;
            float4 va;
            if (gr < N)
                va = *(const float4*)(x + (size_t)gr * FIN + kb + c4 * 4);
            else
                va = make_float4(0.f, 0.f, 0.f, 0.f);
            As[c4 * 4 + 0][lr] = va.x;
            As[c4 * 4 + 1][lr] = va.y;
            As[c4 * 4 + 2][lr] = va.z;
            As[c4 * 4 + 3][lr] = va.w;

            // W rows: bn+lr is always < 512
            float4 vb = *(const float4*)(W + (size_t)(bn + lr) * FIN + kb + c4 * 4);
            Bs[c4 * 4 + 0][lr] = vb.x;
            Bs[c4 * 4 + 1][lr] = vb.y;
            Bs[c4 * 4 + 2][lr] = vb.z;
            Bs[c4 * 4 + 3][lr] = vb.w;
        }
        __syncthreads();

#pragma unroll
        for (int kk = 0; kk < BK; kk++) {
            float a[4], b[4];
            *(float4*)a = *(const float4*)&As[kk][ty * 4];
            *(float4*)b = *(const float4*)&Bs[kk][tx * 4];
#pragma unroll
            for (int i = 0; i < 4; i++)
#pragma unroll
                for (int j = 0; j < 4; j++)
                    acc[i][j] = fmaf(a[i], b[j], acc[i][j]);
        }
        __syncthreads();
    }

    // BN=64 divides 256, so a whole tile is entirely in the q half or k half.
    const float scale = (bn < FQK) ? SCALING : 1.0f;
#pragma unroll
    for (int i = 0; i < 4; i++) {
        const int row = bm + ty * 4 + i;
        if (row < N) {
            float4 v;
            v.x = acc[i][0] * scale;
            v.y = acc[i][1] * scale;
            v.z = acc[i][2] * scale;
            v.w = acc[i][3] * scale;
            *(float4*)(qk + (size_t)row * NQK + bn + tx * 4) = v;
        }
    }
}

// ---------------------------------------------------------------------------
// Kernel 2: per-edge ex[e] = exp( q[src[e]] . k[dest[e]] ). One warp per edge.
// ei is int32 (JAX x64 disabled -> int64 in the reference is int32 on device).
// ---------------------------------------------------------------------------
__global__ __launch_bounds__(256)
void edge_dot_kernel(const int* __restrict__ ei,
                     const float* __restrict__ qk,
                     float* __restrict__ out,
                     int E)
{
    const int w    = (blockIdx.x * blockDim.x + threadIdx.x) >> 5;
    const int lane = threadIdx.x & 31;
    if (w >= E) return;

    const int s = ei[w];
    const int d = ei[(size_t)E + w];

    const float4* qp = (const float4*)(qk + (size_t)s * NQK);          // q row
    const float4* kp = (const float4*)(qk + (size_t)d * NQK + FQK);    // k row

    float4 q0 = qp[lane];
    float4 q1 = qp[lane + 32];
    float4 k0 = kp[lane];
    float4 k1 = kp[lane + 32];

    float dot = q0.x * k0.x + q0.y * k0.y + q0.z * k0.z + q0.w * k0.w
              + q1.x * k1.x + q1.y * k1.y + q1.z * k1.z + q1.w * k1.w;

#pragma unroll
    for (int off = 16; off > 0; off >>= 1)
        dot += __shfl_xor_sync(0xffffffffu, dot, off);

    if (lane == 0) out[w] = __expf(dot);
}

// ---------------------------------------------------------------------------
// Kernel 3: deterministic segment sum over sorted src.
// One warp per node: binary-search the edge range, fixed-order reduction.
// ---------------------------------------------------------------------------
__device__ __forceinline__ int lower_bound_i(const int* __restrict__ a,
                                             int n, int v)
{
    int lo = 0, hi = n;
    while (lo < hi) {
        int mid = (lo + hi) >> 1;
        if (a[mid] < v) lo = mid + 1; else hi = mid;
    }
    return lo;
}

__global__ __launch_bounds__(256)
void segsum_kernel(const int* __restrict__ src,
                   const float* __restrict__ ex,
                   float* __restrict__ expsum,
                   int E, int N)
{
    const int w    = (blockIdx.x * blockDim.x + threadIdx.x) >> 5;
    const int lane = threadIdx.x & 31;
    if (w >= N) return;

    const int lo = lower_bound_i(src, E, w);
    const int hi = lower_bound_i(src, E, w + 1);

    float s = 0.0f;
    for (int i = lo + lane; i < hi; i += 32)
        s += ex[i];

#pragma unroll
    for (int off = 16; off > 0; off >>= 1)
        s += __shfl_xor_sync(0xffffffffu, s, off);

    if (lane == 0) expsum[w] = s;
}

// ---------------------------------------------------------------------------
// Kernel 4: out[e] = ex[e] / expsum[src[e]]
// ---------------------------------------------------------------------------
__global__ __launch_bounds__(256)
void divide_kernel(const int* __restrict__ src,
                   const float* __restrict__ expsum,
                   float* __restrict__ out,
                   int E)
{
    const int e = blockIdx.x * blockDim.x + threadIdx.x;
    if (e >= E) return;
    const int s = src[e];
    out[e] = out[e] / expsum[s];
}

// ---------------------------------------------------------------------------
extern "C" void kernel_launch(void* const* d_in, const int* in_sizes, int n_in,
                              void* d_out, int out_size)
{
    const float* x   = (const float*)d_in[0];
    const int*   ei  = (const int*)d_in[1];
    const float* W   = (const float*)d_in[2];
    float*       out = (float*)d_out;

    const int N = in_sizes[0] / FIN;     // 20000
    const int E = in_sizes[1] / 2;       // 640000

    float* qk;     cudaGetSymbolAddress((void**)&qk,     g_qk);
    float* expsum; cudaGetSymbolAddress((void**)&expsum, g_expsum);

    // 1) projection GEMM
    {
        dim3 grid(NQK / BN, (N + BM - 1) / BM);
        gemm_qk_kernel<<<grid, 256>>>(x, W, qk, N);
    }
    // 2) per-edge exp(q.k)  (one warp per edge)
    {
        int blocks = (E * 32 + 255) / 256;
        edge_dot_kernel<<<blocks, 256>>>(ei, qk, out, E);
    }
    // 3) deterministic segment sums (one warp per node)
    {
        int blocks = (N * 32 + 255) / 256;
        segsum_kernel<<<blocks, 256>>>(ei, out, expsum, E, N);
    }
    // 4) normalize
    {
        int blocks = (E + 255) / 256;
        divide_kernel<<<blocks, 256>>>(ei, expsum, out, E);
    }
}

// round 4
// speedup vs baseline: 2.0077x; 2.0077x over previous
#include <cuda_runtime.h>
#include <cuda_bf16.h>
#include <mma.h>
#include <stdint.h>

using namespace nvcuda;

// Problem constants (fixed by the dataset)
#define FIN   256
#define FQK   256
#define NQK   (2 * FQK)          // 512
#define MAXN  20000
#define MROWS 20096              // 157 * 128, padded for unguarded stores
#define SCALING 0.0625f          // FQK^-0.5

// Scratch (no allocation allowed in kernel_launch)
__device__ float g_qk[(size_t)MROWS * NQK];

// ===========================================================================
// Kernel 1: qk = x @ W^T via WMMA bf16, 3-term bf16 split for fp32 accuracy.
//   x: [N,256] f32 row-major, W: [512,256] f32 row-major.
//   C[i,j] = dot(x[i,:], W[j,:]) ; cols < 256 scaled by 1/16.
// CTA tile: 128 (m) x 64 (n), K chunked by 64. 8 warps, warp = 16 x 64 strip.
// ===========================================================================
#define BM 128
#define BN 64
#define KC 64
#define LDA 72                  // padded smem leading dims (bf16 elements)
#define LDB 72

// dynamic smem layout in bf16 elements
#define SA_HI 0
#define SA_LO (SA_HI + BM * LDA)             // 9216
#define SB_HI (SA_LO + BM * LDA)             // 18432
#define SB_LO (SB_HI + BN * LDB)             // 23040
#define SM_ELEMS (SB_LO + BN * LDB)          // 27648 bf16 = 55296 B

__global__ __launch_bounds__(256)
void gemm_qk_wmma(const float* __restrict__ x,
                  const float* __restrict__ W,
                  float* __restrict__ qk,
                  int N)
{
    extern __shared__ __nv_bfloat16 sm[];
    const int tid = threadIdx.x;
    const int wid = tid >> 5;
    const int m0  = blockIdx.y * BM;
    const int n0  = blockIdx.x * BN;
    const float scale = (n0 < FQK) ? SCALING : 1.0f;

    wmma::fragment<wmma::accumulator, 16, 16, 16, float> acc[4];
#pragma unroll
    for (int f = 0; f < 4; ++f) wmma::fill_fragment(acc[f], 0.0f);

    for (int kc = 0; kc < FIN; kc += KC) {
        // ---- load + split A tile: 128 x 64 floats -> hi/lo bf16 ----
        // 2048 float4s total; each of 256 threads does 8.
#pragma unroll
        for (int i = 0; i < 8; ++i) {
            const int idx = tid + i * 256;       // 0..2047
            const int r   = idx >> 4;            // row 0..127
            const int c4  = idx & 15;            // float4 col 0..15
            const int m   = m0 + r;
            float4 v = (m < N)
                ? *(const float4*)(x + (size_t)m * FIN + kc + c4 * 4)
                : make_float4(0.f, 0.f, 0.f, 0.f);
            const int off = r * LDA + c4 * 4;
            float e[4] = {v.x, v.y, v.z, v.w};
#pragma unroll
            for (int t = 0; t < 4; ++t) {
                __nv_bfloat16 h = __float2bfloat16(e[t]);
                sm[SA_HI + off + t] = h;
                sm[SA_LO + off + t] = __float2bfloat16(e[t] - __bfloat162float(h));
            }
        }
        // ---- load + split B tile: 64 x 64 floats (W rows n0..n0+63) ----
#pragma unroll
        for (int i = 0; i < 4; ++i) {
            const int idx = tid + i * 256;       // 0..1023
            const int r   = idx >> 4;            // 0..63
            const int c4  = idx & 15;
            float4 v = *(const float4*)(W + (size_t)(n0 + r) * FIN + kc + c4 * 4);
            const int off = r * LDB + c4 * 4;
            float e[4] = {v.x, v.y, v.z, v.w};
#pragma unroll
            for (int t = 0; t < 4; ++t) {
                __nv_bfloat16 h = __float2bfloat16(e[t]);
                sm[SB_HI + off + t] = h;
                sm[SB_LO + off + t] = __float2bfloat16(e[t] - __bfloat162float(h));
            }
        }
        __syncthreads();

        // ---- compute: warp strip rows [16*wid, 16*wid+16) ----
        const __nv_bfloat16* aHi = sm + SA_HI + wid * 16 * LDA;
        const __nv_bfloat16* aLo = sm + SA_LO + wid * 16 * LDA;
#pragma unroll
        for (int ks = 0; ks < KC / 16; ++ks) {
            wmma::fragment<wmma::matrix_a, 16, 16, 16, __nv_bfloat16, wmma::row_major> ah, al;
            wmma::load_matrix_sync(ah, aHi + ks * 16, LDA);
            wmma::load_matrix_sync(al, aLo + ks * 16, LDA);
#pragma unroll
            for (int nf = 0; nf < 4; ++nf) {
                // B[k][n] = W[n][k] -> col_major view of W-row storage
                wmma::fragment<wmma::matrix_b, 16, 16, 16, __nv_bfloat16, wmma::col_major> bh, bl;
                const __nv_bfloat16* bHi = sm + SB_HI + nf * 16 * LDB + ks * 16;
                const __nv_bfloat16* bLo = sm + SB_LO + nf * 16 * LDB + ks * 16;
                wmma::load_matrix_sync(bh, bHi, LDB);
                wmma::load_matrix_sync(bl, bLo, LDB);
                wmma::mma_sync(acc[nf], ah, bh, acc[nf]);
                wmma::mma_sync(acc[nf], ah, bl, acc[nf]);
                wmma::mma_sync(acc[nf], al, bh, acc[nf]);
            }
        }
        __syncthreads();
    }

    // ---- epilogue: scale + store (qk rows padded to MROWS, unguarded) ----
#pragma unroll
    for (int nf = 0; nf < 4; ++nf) {
#pragma unroll
        for (int t = 0; t < acc[nf].num_elements; ++t)
            acc[nf].x[t] *= scale;
        float* dst = qk + (size_t)(m0 + wid * 16) * NQK + n0 + nf * 16;
        wmma::store_matrix_sync(dst, acc[nf], NQK, wmma::mem_row_major);
    }
}

// ===========================================================================
// Kernel 2: fused per-node edge pass. One warp per src node:
//   q row in registers; per edge: gather k[dest], dot, exp, in-order sum;
//   then normalized write. Deterministic.
// ===========================================================================
__device__ __forceinline__ int lower_bound_i(const int* __restrict__ a,
                                             int n, int v)
{
    int lo = 0, hi = n;
    while (lo < hi) {
        int mid = (lo + hi) >> 1;
        if (a[mid] < v) lo = mid + 1; else hi = mid;
    }
    return lo;
}

__global__ __launch_bounds__(256)
void edge_fused_kernel(const int* __restrict__ ei,
                       const float* __restrict__ qk,
                       float* __restrict__ out,
                       int E, int N)
{
    const int node = (blockIdx.x * blockDim.x + threadIdx.x) >> 5;
    const int lane = threadIdx.x & 31;
    if (node >= N) return;

    const int lo = lower_bound_i(ei, E, node);
    const int hi = lower_bound_i(ei, E, node + 1);
    if (lo >= hi) return;
    const int deg = hi - lo;

    const float4* qp = (const float4*)(qk + (size_t)node * NQK);
    const float4 q0 = qp[lane];
    const float4 q1 = qp[lane + 32];

    const int* __restrict__ dest = ei + E;
    float sum = 0.0f;

    if (deg <= 256) {
        float exbuf[8];
        // software-pipelined k gather
        int d0 = dest[lo];
        const float4* kp = (const float4*)(qk + (size_t)d0 * NQK + FQK);
        float4 k0 = kp[lane];
        float4 k1 = kp[lane + 32];
        for (int j = lo; j < hi; ++j) {
            float4 c0 = k0, c1 = k1;
            if (j + 1 < hi) {
                int dn = dest[j + 1];
                const float4* kn = (const float4*)(qk + (size_t)dn * NQK + FQK);
                k0 = kn[lane];
                k1 = kn[lane + 32];
            }
            float dot = q0.x * c0.x + q0.y * c0.y + q0.z * c0.z + q0.w * c0.w
                      + q1.x * c1.x + q1.y * c1.y + q1.z * c1.z + q1.w * c1.w;
#pragma unroll
            for (int o = 16; o > 0; o >>= 1)
                dot += __shfl_xor_sync(0xffffffffu, dot, o);
            float ex = __expf(dot);
            sum += ex;                        // identical across lanes
            int idx = j - lo;
            if ((idx & 31) == lane) exbuf[idx >> 5] = ex;
        }
        float inv = 1.0f / sum;
#pragma unroll 1
        for (int s = 0; s * 32 + lane < deg; ++s)
            out[lo + s * 32 + lane] = exbuf[s] * inv;
    } else {
        // spill path (degrees here average 32; effectively never taken)
        for (int j = lo; j < hi; ++j) {
            int d = dest[j];
            const float4* kp = (const float4*)(qk + (size_t)d * NQK + FQK);
            float4 c0 = kp[lane];
            float4 c1 = kp[lane + 32];
            float dot = q0.x * c0.x + q0.y * c0.y + q0.z * c0.z + q0.w * c0.w
                      + q1.x * c1.x + q1.y * c1.y + q1.z * c1.z + q1.w * c1.w;
#pragma unroll
            for (int o = 16; o > 0; o >>= 1)
                dot += __shfl_xor_sync(0xffffffffu, dot, o);
            float ex = __expf(dot);
            sum += ex;
            if (((j - lo) & 31) == lane) out[j] = ex;
        }
        __syncwarp();
        float inv = 1.0f / sum;
        for (int j = lo + lane; j < hi; j += 32)
            out[j] *= inv;
    }
}

// ===========================================================================
extern "C" void kernel_launch(void* const* d_in, const int* in_sizes, int n_in,
                              void* d_out, int out_size)
{
    const float* x   = (const float*)d_in[0];
    const int*   ei  = (const int*)d_in[1];
    const float* W   = (const float*)d_in[2];
    float*       out = (float*)d_out;

    const int N = in_sizes[0] / FIN;     // 20000
    const int E = in_sizes[1] / 2;       // 640000

    float* qk;
    cudaGetSymbolAddress((void**)&qk, g_qk);

    // 1) projection GEMM (bf16x3 WMMA)
    {
        cudaFuncSetAttribute(gemm_qk_wmma,
                             cudaFuncAttributeMaxDynamicSharedMemorySize,
                             SM_ELEMS * (int)sizeof(__nv_bfloat16));
        dim3 grid(NQK / BN, (N + BM - 1) / BM);
        gemm_qk_wmma<<<grid, 256, SM_ELEMS * sizeof(__nv_bfloat16)>>>(x, W, qk, N);
    }
    // 2) fused edge dot + scatter softmax (one warp per node)
    {
        int blocks = (N * 32 + 255) / 256;
        edge_fused_kernel<<<blocks, 256>>>(ei, qk, out, E, N);
    }
}